// round 6
// baseline (speedup 1.0000x reference)
#include <cuda_runtime.h>
#include <math.h>
#include <float.h>

// Problem constants (fixed by the dataset)
#define BB 1024
#define LL 81
#define HH 8
#define DD 64
#define UU 10
#define NSAMP 41
#define WS 9
#define QSTR 68
#define KSTR 68

#define NTHREADS 256

// Dynamic SMEM layout (floats):
//   hdr 16 (mbarrier) | Qs 5508 | Ks 5508 | Vs 5184 | bias 289 | Ms 84
//   pmx 924 | psm 924 | upd 640 | topi 16 ints | rank_of 81 ints
#define SM_FLOATS (16 + 81*QSTR + 81*KSTR + 81*DD + 289 + 84 + 924 + 924 + 640)
#define SM_BYTES  (SM_FLOATS*4 + (16 + 81)*4)

__device__ __forceinline__ unsigned long long ffma2(unsigned long long a,
                                                    unsigned long long b,
                                                    unsigned long long c) {
    unsigned long long d;
    asm("fma.rn.f32x2 %0, %1, %2, %3;" : "=l"(d) : "l"(a), "l"(b), "l"(c));
    return d;
}
__device__ __forceinline__ float f2sum(unsigned long long a) {
    return __uint_as_float((unsigned)(a & 0xffffffffull)) +
           __uint_as_float((unsigned)(a >> 32));
}
__device__ __forceinline__ unsigned smem_u32(const void* p) {
    return (unsigned)__cvta_generic_to_shared(p);
}

__global__ __launch_bounds__(NTHREADS, 3)
void prob_attn_kernel(const float* __restrict__ q_in,
                      const float* __restrict__ k_in,
                      const float* __restrict__ v_in,
                      const float* __restrict__ bias_in,
                      float* __restrict__ out_ctx,
                      float* __restrict__ out_attn)
{
    extern __shared__ float sm[];
    float* Qs    = sm + 16;
    float* Ks    = Qs + 81*QSTR;
    float* Vs    = Ks + 81*KSTR;
    float* biass = Vs + 81*DD;
    float* Ms    = biass + 289;
    float* pmx   = Ms + 84;
    float* psm   = pmx + 924;
    float* upds  = psm + 924;
    int*   topi  = (int*)(upds + 640);
    int*   rank_of = topi + 16;

    const int tid  = threadIdx.x;
    const int warp = tid >> 5;
    const int lane = tid & 31;

    const int blk = blockIdx.x;
    const int b = blk >> 3;
    const int h = blk & 7;

    const size_t base = ((size_t)b * LL * HH + h) * DD;
    const float* qb = q_in + base;
    const float* kb = k_in + base;
    const float* vb = v_in + base;

    const unsigned mbar = smem_u32(sm);   // 8B-aligned mbarrier in hdr

    // ---- Phase A: async bulk copies (DMA) for Q/K/V rows; bias via LDG ----
    if (warp == 0) {
        if (lane == 0) {
            asm volatile("mbarrier.init.shared.b64 [%0], 1;" :: "r"(mbar) : "memory");
        }
        __syncwarp();
        if (lane == 0) {
            asm volatile("mbarrier.arrive.expect_tx.shared.b64 _, [%0], %1;"
                         :: "r"(mbar), "r"(243 * 256) : "memory");
        }
        __syncwarp();
        for (int i = lane; i < 243; i += 32) {
            int a   = i / 81;          // 0=Q, 1=K, 2=V
            int row = i - a * 81;
            const float* src = (a == 0 ? qb : (a == 1 ? kb : vb)) + (size_t)row * (HH * DD);
            float* dstp = (a == 0 ? Qs + row * QSTR
                                  : (a == 1 ? Ks + row * KSTR : Vs + row * DD));
            unsigned dst = smem_u32(dstp);
            asm volatile(
                "cp.async.bulk.shared::cta.global.mbarrier::complete_tx::bytes "
                "[%0], [%1], %2, [%3];"
                :: "r"(dst), "l"(src), "r"(256), "r"(mbar) : "memory");
        }
    } else {
        for (int i = tid - 32; i < 289; i += NTHREADS - 32) biass[i] = bias_in[i];
        if (tid - 32 < LL) rank_of[tid - 32] = -1;
    }
    __syncthreads();
    // wait for bulk copies (parity 0)
    {
        unsigned done;
        asm volatile(
            "{\n\t.reg .pred p;\n\t"
            "mbarrier.try_wait.parity.acquire.cta.shared::cta.b64 p, [%1], 0;\n\t"
            "selp.b32 %0, 1, 0, p;\n\t}"
            : "=r"(done) : "r"(mbar) : "memory");
        while (!done) {
            asm volatile(
                "{\n\t.reg .pred p;\n\t"
                "mbarrier.try_wait.parity.acquire.cta.shared::cta.b64 p, [%1], 0, 0x989680;\n\t"
                "selp.b32 %0, 1, 0, p;\n\t}"
                : "=r"(done) : "r"(mbar) : "memory");
        }
    }

    // ---- Phase B: sampled scores, 4q x 4s per thread, packed f32x2 FMA ----
    if (tid < 231) {
        const int st = tid / 21;        // 0..10
        const int qt = tid - st * 21;   // 0..20

        const float* Qr[4];
        const float* Kr[4];
        #pragma unroll
        for (int i = 0; i < 4; i++) {
            int q = qt + 21 * i; if (q > 80) q = 80;
            Qr[i] = Qs + q * QSTR;
        }
        #pragma unroll
        for (int j = 0; j < 4; j++) {
            int s = st + 11 * j; if (s > 40) s = 40;
            Kr[j] = Ks + (2 * s) * KSTR;
        }

        unsigned long long acc2[4][4];
        #pragma unroll
        for (int i = 0; i < 4; i++)
            #pragma unroll
            for (int j = 0; j < 4; j++) acc2[i][j] = 0ull;

        #pragma unroll 2
        for (int d = 0; d < DD; d += 4) {
            ulonglong2 qv[4], kv[4];
            #pragma unroll
            for (int i = 0; i < 4; i++) qv[i] = *(const ulonglong2*)(Qr[i] + d);
            #pragma unroll
            for (int j = 0; j < 4; j++) kv[j] = *(const ulonglong2*)(Kr[j] + d);
            #pragma unroll
            for (int i = 0; i < 4; i++)
                #pragma unroll
                for (int j = 0; j < 4; j++) {
                    acc2[i][j] = ffma2(qv[i].x, kv[j].x, acc2[i][j]);
                    acc2[i][j] = ffma2(qv[i].y, kv[j].y, acc2[i][j]);
                }
        }

        #pragma unroll
        for (int i = 0; i < 4; i++) {
            int q = qt + 21 * i;
            if (q < LL) {
                float mx = -FLT_MAX, smv = 0.0f;
                #pragma unroll
                for (int j = 0; j < 4; j++) {
                    if (st + 11 * j < NSAMP) {
                        float v = f2sum(acc2[i][j]);
                        mx = fmaxf(mx, v);
                        smv += v;
                    }
                }
                pmx[st * 84 + q] = mx;
                psm[st * 84 + q] = smv;
            }
        }
    }
    __syncthreads();

    // reduce partials -> M[q] = max_s - sum_s / 81
    if (tid < LL) {
        float mx = -FLT_MAX, smv = 0.0f;
        #pragma unroll
        for (int st = 0; st < 11; st++) {
            mx = fmaxf(mx, pmx[st * 84 + tid]);
            smv += psm[st * 84 + tid];
        }
        Ms[tid] = mx - smv * (1.0f / 81.0f);
    }
    __syncthreads();

    float* csum = pmx;   // reuse after this sync (128 floats)

    // ---- Phase C (warp 0): top-10 ; warps 5-6: cumsum chunk sums (overlap) ----
    if (warp == 0) {
        float m0 = (lane      < LL) ? Ms[lane]      : -FLT_MAX;
        float m1 = (lane + 32 < LL) ? Ms[lane + 32] : -FLT_MAX;
        float m2 = (lane + 64 < LL) ? Ms[lane + 64] : -FLT_MAX;
        #pragma unroll
        for (int r = 0; r < UU; r++) {
            float bv = m0; int bi = lane;
            if (m1 > bv) { bv = m1; bi = lane + 32; }
            if (m2 > bv) { bv = m2; bi = lane + 64; }
            #pragma unroll
            for (int o = 16; o > 0; o >>= 1) {
                float ov = __shfl_xor_sync(0xffffffffu, bv, o);
                int   oi = __shfl_xor_sync(0xffffffffu, bi, o);
                if (ov > bv || (ov == bv && oi < bi)) { bv = ov; bi = oi; }
            }
            if (lane == 0) { topi[r] = bi; rank_of[bi] = r; }
            if (bi == lane)           m0 = -FLT_MAX;
            else if (bi == lane + 32) m1 = -FLT_MAX;
            else if (bi == lane + 64) m2 = -FLT_MAX;
        }
    } else if (warp == 5 || warp == 6) {
        const int c = warp - 5;          // chunk 0 or 1
        const int l0 = c * 27;
        float s0 = 0.0f, s1 = 0.0f;
        #pragma unroll 9
        for (int l = l0; l < l0 + 27; l++) {
            s0 += Vs[l * DD + lane];
            s1 += Vs[l * DD + lane + 32];
        }
        csum[c * 64 + lane]      = s0;
        csum[c * 64 + lane + 32] = s1;
    }
    __syncthreads();

    // ---- Phase D (warps 0-4): 2 rows per warp (scores+softmax+PV).
    //      Warps 5-7 concurrently: cumsum + store of the 71 non-selected rows. ----
    const float scale = 0.125f;
    if (warp < 5) {
        const int r0 = 2 * warp, r1 = r0 + 1;
        const float* q0p = Qs + topi[r0] * QSTR;
        const float* q1p = Qs + topi[r1] * QSTR;

        float sc[2][3];
        #pragma unroll
        for (int t = 0; t < 3; t++) {
            int k = lane + t * 32;
            const float* kr = Ks + (k < LL ? k : LL - 1) * KSTR;
            unsigned long long a0 = 0ull, a1 = 0ull;
            #pragma unroll 4
            for (int d = 0; d < DD; d += 4) {
                ulonglong2 kv = *(const ulonglong2*)(kr + d);
                ulonglong2 qa = *(const ulonglong2*)(q0p + d);
                ulonglong2 qc = *(const ulonglong2*)(q1p + d);
                a0 = ffma2(qa.x, kv.x, a0);
                a0 = ffma2(qa.y, kv.y, a0);
                a1 = ffma2(qc.x, kv.x, a1);
                a1 = ffma2(qc.y, kv.y, a1);
            }
            sc[0][t] = f2sum(a0);
            sc[1][t] = f2sum(a1);
        }

        #pragma unroll
        for (int p = 0; p < 2; p++) {
            const int r = r0 + p;
            const int ri = r / WS, rj = r % WS;   // bias row indexed by RANK (ref quirk)
            float mx = -FLT_MAX;
            #pragma unroll
            for (int t = 0; t < 3; t++) {
                int k = lane + t * 32;
                if (k < LL) {
                    int ki = k / WS, kj = k - ki * WS;
                    int bidx = (ri - ki + (WS - 1)) * (2 * WS - 1) + (rj - kj + (WS - 1));
                    sc[p][t] = (sc[p][t] + biass[bidx]) * scale;
                } else {
                    sc[p][t] = -FLT_MAX;
                }
                mx = fmaxf(mx, sc[p][t]);
            }
            #pragma unroll
            for (int o = 16; o > 0; o >>= 1)
                mx = fmaxf(mx, __shfl_xor_sync(0xffffffffu, mx, o));

            float sum = 0.0f;
            #pragma unroll
            for (int t = 0; t < 3; t++) {
                int k = lane + t * 32;
                sc[p][t] = (k < LL) ? __expf(sc[p][t] - mx) : 0.0f;
                sum += sc[p][t];
            }
            #pragma unroll
            for (int o = 16; o > 0; o >>= 1)
                sum += __shfl_xor_sync(0xffffffffu, sum, o);
            const float inv = 1.0f / sum;

            float* ao = out_attn ? out_attn + (((size_t)b * HH + h) * UU + r) * LL : (float*)0;
            #pragma unroll
            for (int t = 0; t < 3; t++) {
                int k = lane + t * 32;
                sc[p][t] *= inv;
                if (ao && k < LL) ao[k] = sc[p][t];
            }
        }

        // PV for both rows: V read once; attn weights broadcast via shfl
        float pa00 = 0.f, pa01 = 0.f, pa10 = 0.f, pa11 = 0.f;
        for (int k = 0; k < LL; k++) {
            float v0 = Vs[k * DD + lane];
            float v1 = Vs[k * DD + lane + 32];
            const int t = k >> 5, sl = k & 31;
            float w0 = __shfl_sync(0xffffffffu,
                         (t == 0 ? sc[0][0] : (t == 1 ? sc[0][1] : sc[0][2])), sl);
            float w1 = __shfl_sync(0xffffffffu,
                         (t == 0 ? sc[1][0] : (t == 1 ? sc[1][1] : sc[1][2])), sl);
            pa00 += w0 * v0; pa01 += w0 * v1;
            pa10 += w1 * v0; pa11 += w1 * v1;
        }
        upds[r0 * DD + lane]      = pa00;
        upds[r0 * DD + lane + 32] = pa01;
        upds[r1 * DD + lane]      = pa10;
        upds[r1 * DD + lane + 32] = pa11;
    } else {
        // warps 5,6,7 -> chunks 0,1,2: cumsum + store non-selected rows
        const int c = warp - 5;
        float acc0 = 0.0f, acc1 = 0.0f;
        if (c > 0) { acc0 += csum[lane];      acc1 += csum[lane + 32]; }
        if (c > 1) { acc0 += csum[64 + lane]; acc1 += csum[64 + lane + 32]; }
        float* ob = out_ctx + base;
        const int l0 = c * 27;
        for (int l = l0; l < l0 + 27; l++) {
            acc0 += Vs[l * DD + lane];
            acc1 += Vs[l * DD + lane + 32];
            if (rank_of[l] < 0) {
                ob[(size_t)l * (HH * DD) + lane]      = acc0;
                ob[(size_t)l * (HH * DD) + lane + 32] = acc1;
            }
        }
    }
    __syncthreads();

    // ---- Phase E: scatter the 10 selected rows from upds ----
    for (int idx = tid; idx < UU * DD; idx += NTHREADS) {
        int r = idx >> 6;
        int d = idx & 63;
        out_ctx[base + (size_t)topi[r] * (HH * DD) + d] = upds[idx];
    }
}

extern "C" void kernel_launch(void* const* d_in, const int* in_sizes, int n_in,
                              void* d_out, int out_size)
{
    const float* q    = (const float*)d_in[0];
    const float* k    = (const float*)d_in[1];
    const float* v    = (const float*)d_in[2];
    const float* bias = (const float*)d_in[3];
    float* out = (float*)d_out;

    const long long ctx_elems  = (long long)BB * LL * HH * DD;
    const long long attn_elems = (long long)BB * HH * UU * LL;
    float* attn_out = ((long long)out_size >= ctx_elems + attn_elems)
                        ? out + ctx_elems : (float*)0;

    cudaFuncSetAttribute(prob_attn_kernel,
                         cudaFuncAttributeMaxDynamicSharedMemorySize, SM_BYTES);
    prob_attn_kernel<<<BB * HH, NTHREADS, SM_BYTES>>>(q, k, v, bias, out, attn_out);
}

// round 7
// speedup vs baseline: 1.1027x; 1.1027x over previous
#include <cuda_runtime.h>
#include <math.h>
#include <float.h>

// Problem constants (fixed by the dataset)
#define BB 1024
#define LL 81
#define HH 8
#define DD 64
#define UU 10
#define NSAMP 41
#define WS 9
#define QSTR 68
#define KSTR 68

#define NTHREADS 256

// Shared memory layout (floats):
//   Qs 5508 | Ks 5508 | Vs 5184 | bias 289 | Ms 84 | pmx 924 | psm 924 | upd 640
//   topi 16 ints | rank_of 81 ints
#define SM_FLOATS (81*QSTR + 81*KSTR + 81*DD + 289 + 84 + 924 + 924 + 640)
#define SM_BYTES  (SM_FLOATS*4 + (16 + 81)*4)

__device__ __forceinline__ unsigned long long ffma2(unsigned long long a,
                                                    unsigned long long b,
                                                    unsigned long long c) {
    unsigned long long d;
    asm("fma.rn.f32x2 %0, %1, %2, %3;" : "=l"(d) : "l"(a), "l"(b), "l"(c));
    return d;
}
__device__ __forceinline__ float f2sum(unsigned long long a) {
    return __uint_as_float((unsigned)(a & 0xffffffffull)) +
           __uint_as_float((unsigned)(a >> 32));
}

__global__ __launch_bounds__(NTHREADS, 3)
void prob_attn_kernel(const float* __restrict__ q_in,
                      const float* __restrict__ k_in,
                      const float* __restrict__ v_in,
                      const float* __restrict__ bias_in,
                      float* __restrict__ out_ctx,
                      float* __restrict__ out_attn)
{
    extern __shared__ float sm[];
    float* Qs    = sm;
    float* Ks    = Qs + 81*QSTR;
    float* Vs    = Ks + 81*KSTR;
    float* biass = Vs + 81*DD;
    float* Ms    = biass + 289;
    float* pmx   = Ms + 84;
    float* psm   = pmx + 924;
    float* upds  = psm + 924;
    int*   topi  = (int*)(upds + 640);
    int*   rank_of = topi + 16;

    const int tid  = threadIdx.x;
    const int warp = tid >> 5;
    const int lane = tid & 31;

    const int blk = blockIdx.x;
    const int b = blk >> 3;
    const int h = blk & 7;

    const size_t base = ((size_t)b * LL * HH + h) * DD;
    const float* qb = q_in + base;
    const float* kb = k_in + base;
    const float* vb = v_in + base;

    // ---- Phase A: load tiles (coalesced float4), bias, init rank map ----
    for (int idx = tid; idx < LL * 16; idx += NTHREADS) {
        int row = idx >> 4;
        int vec = idx & 15;
        size_t goff = (size_t)row * (HH * DD) + vec * 4;
        float4 qv = *(const float4*)(qb + goff);
        float4 kv = *(const float4*)(kb + goff);
        float4 vv = *(const float4*)(vb + goff);
        *(float4*)(Qs + row*QSTR + vec*4) = qv;
        *(float4*)(Ks + row*KSTR + vec*4) = kv;
        *(float4*)(Vs + row*DD   + vec*4) = vv;
    }
    for (int i = tid; i < 289; i += NTHREADS) biass[i] = bias_in[i];
    if (tid < LL) rank_of[tid] = -1;
    __syncthreads();

    // ---- Phase B: sampled scores, 4q x 4s per thread, packed f32x2 FMA.
    //      q rows interleaved stride 21 (adjacent lanes -> adjacent rows,
    //      68-word stride => conflict-free LDS.128); s interleaved stride 11.
    if (tid < 231) {
        const int st = tid / 21;        // 0..10
        const int qt = tid - st * 21;   // 0..20

        const float* Qr[4];
        const float* Kr[4];
        #pragma unroll
        for (int i = 0; i < 4; i++) {
            int q = qt + 21 * i; if (q > 80) q = 80;
            Qr[i] = Qs + q * QSTR;
        }
        #pragma unroll
        for (int j = 0; j < 4; j++) {
            int s = st + 11 * j; if (s > 40) s = 40;
            Kr[j] = Ks + (2 * s) * KSTR;
        }

        unsigned long long acc2[4][4];
        #pragma unroll
        for (int i = 0; i < 4; i++)
            #pragma unroll
            for (int j = 0; j < 4; j++) acc2[i][j] = 0ull;

        #pragma unroll 2
        for (int d = 0; d < DD; d += 4) {
            ulonglong2 qv[4], kv[4];
            #pragma unroll
            for (int i = 0; i < 4; i++) qv[i] = *(const ulonglong2*)(Qr[i] + d);
            #pragma unroll
            for (int j = 0; j < 4; j++) kv[j] = *(const ulonglong2*)(Kr[j] + d);
            #pragma unroll
            for (int i = 0; i < 4; i++)
                #pragma unroll
                for (int j = 0; j < 4; j++) {
                    acc2[i][j] = ffma2(qv[i].x, kv[j].x, acc2[i][j]);
                    acc2[i][j] = ffma2(qv[i].y, kv[j].y, acc2[i][j]);
                }
        }

        #pragma unroll
        for (int i = 0; i < 4; i++) {
            int q = qt + 21 * i;
            if (q < LL) {
                float mx = -FLT_MAX, smv = 0.0f;
                #pragma unroll
                for (int j = 0; j < 4; j++) {
                    if (st + 11 * j < NSAMP) {
                        float v = f2sum(acc2[i][j]);
                        mx = fmaxf(mx, v);
                        smv += v;
                    }
                }
                pmx[st * 84 + q] = mx;
                psm[st * 84 + q] = smv;
            }
        }
    }
    __syncthreads();

    // reduce partials -> M[q] = max_s - sum_s / 81
    if (tid < LL) {
        float mx = -FLT_MAX, smv = 0.0f;
        #pragma unroll
        for (int st = 0; st < 11; st++) {
            mx = fmaxf(mx, pmx[st * 84 + tid]);
            smv += psm[st * 84 + tid];
        }
        Ms[tid] = mx - smv * (1.0f / 81.0f);
    }
    __syncthreads();

    float* csum = pmx;   // reuse after this sync (128 floats)

    // ---- Phase C (warp 0): top-10 ; warps 5-6: cumsum chunk sums (overlap) ----
    if (warp == 0) {
        float m0 = (lane      < LL) ? Ms[lane]      : -FLT_MAX;
        float m1 = (lane + 32 < LL) ? Ms[lane + 32] : -FLT_MAX;
        float m2 = (lane + 64 < LL) ? Ms[lane + 64] : -FLT_MAX;
        #pragma unroll
        for (int r = 0; r < UU; r++) {
            float bv = m0; int bi = lane;
            if (m1 > bv) { bv = m1; bi = lane + 32; }
            if (m2 > bv) { bv = m2; bi = lane + 64; }
            #pragma unroll
            for (int o = 16; o > 0; o >>= 1) {
                float ov = __shfl_xor_sync(0xffffffffu, bv, o);
                int   oi = __shfl_xor_sync(0xffffffffu, bi, o);
                if (ov > bv || (ov == bv && oi < bi)) { bv = ov; bi = oi; }
            }
            if (lane == 0) { topi[r] = bi; rank_of[bi] = r; }
            if (bi == lane)           m0 = -FLT_MAX;
            else if (bi == lane + 32) m1 = -FLT_MAX;
            else if (bi == lane + 64) m2 = -FLT_MAX;
        }
    } else if (warp == 5 || warp == 6) {
        const int c = warp - 5;          // chunk 0 or 1
        const int l0 = c * 27;
        float s0 = 0.0f, s1 = 0.0f;
        #pragma unroll 9
        for (int l = l0; l < l0 + 27; l++) {
            s0 += Vs[l * DD + lane];
            s1 += Vs[l * DD + lane + 32];
        }
        csum[c * 64 + lane]      = s0;
        csum[c * 64 + lane + 32] = s1;
    }
    __syncthreads();

    // ---- Phase D (warps 0-4): 2 rows per warp (scores+softmax+PV).
    //      Warps 5-7 concurrently: cumsum + store of the 71 non-selected rows. ----
    const float scale = 0.125f;
    if (warp < 5) {
        const int r0 = 2 * warp, r1 = r0 + 1;
        const float* q0p = Qs + topi[r0] * QSTR;
        const float* q1p = Qs + topi[r1] * QSTR;

        float sc[2][3];
        #pragma unroll
        for (int t = 0; t < 3; t++) {
            int k = lane + t * 32;
            const float* kr = Ks + (k < LL ? k : LL - 1) * KSTR;
            unsigned long long a0 = 0ull, a1 = 0ull;
            #pragma unroll 4
            for (int d = 0; d < DD; d += 4) {
                ulonglong2 kv = *(const ulonglong2*)(kr + d);
                ulonglong2 qa = *(const ulonglong2*)(q0p + d);
                ulonglong2 qc = *(const ulonglong2*)(q1p + d);
                a0 = ffma2(qa.x, kv.x, a0);
                a0 = ffma2(qa.y, kv.y, a0);
                a1 = ffma2(qc.x, kv.x, a1);
                a1 = ffma2(qc.y, kv.y, a1);
            }
            sc[0][t] = f2sum(a0);
            sc[1][t] = f2sum(a1);
        }

        #pragma unroll
        for (int p = 0; p < 2; p++) {
            const int r = r0 + p;
            const int ri = r / WS, rj = r % WS;   // bias row indexed by RANK (ref quirk)
            float mx = -FLT_MAX;
            #pragma unroll
            for (int t = 0; t < 3; t++) {
                int k = lane + t * 32;
                if (k < LL) {
                    int ki = k / WS, kj = k - ki * WS;
                    int bidx = (ri - ki + (WS - 1)) * (2 * WS - 1) + (rj - kj + (WS - 1));
                    sc[p][t] = (sc[p][t] + biass[bidx]) * scale;
                } else {
                    sc[p][t] = -FLT_MAX;
                }
                mx = fmaxf(mx, sc[p][t]);
            }
            #pragma unroll
            for (int o = 16; o > 0; o >>= 1)
                mx = fmaxf(mx, __shfl_xor_sync(0xffffffffu, mx, o));

            float sum = 0.0f;
            #pragma unroll
            for (int t = 0; t < 3; t++) {
                int k = lane + t * 32;
                sc[p][t] = (k < LL) ? __expf(sc[p][t] - mx) : 0.0f;
                sum += sc[p][t];
            }
            #pragma unroll
            for (int o = 16; o > 0; o >>= 1)
                sum += __shfl_xor_sync(0xffffffffu, sum, o);
            const float inv = 1.0f / sum;

            float* ao = out_attn ? out_attn + (((size_t)b * HH + h) * UU + r) * LL : (float*)0;
            #pragma unroll
            for (int t = 0; t < 3; t++) {
                int k = lane + t * 32;
                sc[p][t] *= inv;
                if (ao && k < LL) ao[k] = sc[p][t];
            }
        }

        // PV for both rows: V read once; attn weights broadcast via shfl
        float pa00 = 0.f, pa01 = 0.f, pa10 = 0.f, pa11 = 0.f;
        for (int k = 0; k < LL; k++) {
            float v0 = Vs[k * DD + lane];
            float v1 = Vs[k * DD + lane + 32];
            const int t = k >> 5, sl = k & 31;
            float w0 = __shfl_sync(0xffffffffu,
                         (t == 0 ? sc[0][0] : (t == 1 ? sc[0][1] : sc[0][2])), sl);
            float w1 = __shfl_sync(0xffffffffu,
                         (t == 0 ? sc[1][0] : (t == 1 ? sc[1][1] : sc[1][2])), sl);
            pa00 += w0 * v0; pa01 += w0 * v1;
            pa10 += w1 * v0; pa11 += w1 * v1;
        }
        upds[r0 * DD + lane]      = pa00;
        upds[r0 * DD + lane + 32] = pa01;
        upds[r1 * DD + lane]      = pa10;
        upds[r1 * DD + lane + 32] = pa11;
    } else {
        // warps 5,6,7 -> chunks 0,1,2: cumsum + store non-selected rows
        const int c = warp - 5;
        float acc0 = 0.0f, acc1 = 0.0f;
        if (c > 0) { acc0 += csum[lane];      acc1 += csum[lane + 32]; }
        if (c > 1) { acc0 += csum[64 + lane]; acc1 += csum[64 + lane + 32]; }
        float* ob = out_ctx + base;
        const int l0 = c * 27;
        for (int l = l0; l < l0 + 27; l++) {
            acc0 += Vs[l * DD + lane];
            acc1 += Vs[l * DD + lane + 32];
            if (rank_of[l] < 0) {
                ob[(size_t)l * (HH * DD) + lane]      = acc0;
                ob[(size_t)l * (HH * DD) + lane + 32] = acc1;
            }
        }
    }
    __syncthreads();

    // ---- Phase E: scatter the 10 selected rows from upds ----
    for (int idx = tid; idx < UU * DD; idx += NTHREADS) {
        int r = idx >> 6;
        int d = idx & 63;
        out_ctx[base + (size_t)topi[r] * (HH * DD) + d] = upds[idx];
    }
}

extern "C" void kernel_launch(void* const* d_in, const int* in_sizes, int n_in,
                              void* d_out, int out_size)
{
    const float* q    = (const float*)d_in[0];
    const float* k    = (const float*)d_in[1];
    const float* v    = (const float*)d_in[2];
    const float* bias = (const float*)d_in[3];
    float* out = (float*)d_out;

    const long long ctx_elems  = (long long)BB * LL * HH * DD;
    const long long attn_elems = (long long)BB * HH * UU * LL;
    float* attn_out = ((long long)out_size >= ctx_elems + attn_elems)
                        ? out + ctx_elems : (float*)0;

    cudaFuncSetAttribute(prob_attn_kernel,
                         cudaFuncAttributeMaxDynamicSharedMemorySize, SM_BYTES);
    prob_attn_kernel<<<BB * HH, NTHREADS, SM_BYTES>>>(q, k, v, bias, out, attn_out);
}